// round 16
// baseline (speedup 1.0000x reference)
#include <cuda_runtime.h>

typedef unsigned long long ull;

#define NG 8           // batch groups (32 batches each)
#define NP 16          // column partitions (16 hidden cols each)
#define NBLK (NG*NP)   // 128 CTAs
#define NT 256         // 8 warps
// smem floats: sP1 25600 + sP2 12800 + h0s 8192 + h1s 8192 + red2 256 + ybuf 32
#define SM_FLOATS (25600+12800+8192+8192+256+32)
#define SMEM_BYTES (SM_FLOATS*4)

// ---------------- static device scratch (no allocation) ----------------
__device__ float d_pP1[NP*256*100];   // [p][k(str100)][cp][ Whh0 r0 r1 z0 z1 n0 n1 | Wih1 ... ]
__device__ float d_pP2[NP*256*50];    // [p][k(str50)][cp][ Whh1 r0 r1 z0 z1 n0 n1 ]
__device__ float d_pD [NP*256*50];    // Wd_hh, same layout as P2
__device__ float d_xT[512*256];       // x transposed [t][b]
__device__ float d_h0g[2*NG*8192];    // [par][g][col256][b32]
__device__ float d_h1g[2*NG*8192];
__device__ float d_party[2*NP*NG*32]; // [par][p][g][b]
__device__ unsigned d_f0[NG*16];      // per-CTA monotonic flags: h0 published
__device__ unsigned d_f1[NG*16];      // h1 (+party) published

// ---------------- prep ----------------
__global__ void prep_kernel(const float* __restrict__ Whh0, const float* __restrict__ Wih1,
                            const float* __restrict__ Whh1, const float* __restrict__ Wdhh,
                            const float* __restrict__ x)
{
    int idx = blockIdx.x*blockDim.x + threadIdx.x;
    int stride = gridDim.x*blockDim.x;
    if (idx < NG*16) { d_f0[idx] = 0u; d_f1[idx] = 0u; }
    for (int i = idx; i < NP*256*96; i += stride) {
        int q = i % 12, cp = (i/12) & 7, k = (i/96) & 255, p = i/24576;
        int qq = (q < 6) ? q : q - 6;
        int gate = qq >> 1, cl = qq & 1;
        int col = p*16 + cp*2 + cl;
        int src = (gate*256 + col)*256 + k;
        d_pP1[p*25600 + k*100 + cp*12 + q] = (q < 6) ? Whh0[src] : Wih1[src];
    }
    for (int i = idx; i < NP*256*48; i += stride) {
        int q = i % 6, cp = (i/6) & 7, k = (i/48) & 255, p = i/12288;
        int gate = q >> 1, cl = q & 1;
        int col = p*16 + cp*2 + cl;
        int src = (gate*256 + col)*256 + k;
        int dst = p*12800 + k*50 + cp*6 + q;
        d_pP2[dst] = Whh1[src];
        d_pD[dst]  = Wdhh[src];
    }
    for (int i = idx; i < 512*256; i += stride)
        d_xT[i] = x[(i & 255)*512 + (i >> 8)];
    for (int i = idx; i < 2*NG*8192; i += stride)
        d_h1g[i] = 0.0f;   // h1(0) reads must see zeros
}

// ---------------- helpers ----------------
__device__ __forceinline__ ull splat2(float v){ ull r; asm("mov.b64 %0, {%1,%1};" : "=l"(r) : "f"(v)); return r; }
__device__ __forceinline__ void fma2(ull &d, ull a, ull b){ asm("fma.rn.f32x2 %0, %1, %2, %0;" : "+l"(d) : "l"(a), "l"(b)); }
__device__ __forceinline__ ull add2(ull a, ull b){ ull r; asm("add.rn.f32x2 %0, %1, %2;" : "=l"(r) : "l"(a), "l"(b)); return r; }
__device__ __forceinline__ float2 unp(ull v){ float2 f; asm("mov.b64 {%0,%1}, %2;" : "=f"(f.x), "=f"(f.y) : "l"(v)); return f; }
__device__ __forceinline__ float sigf(float v){ return 1.0f/(1.0f + __expf(-v)); }
__device__ __forceinline__ float tanh_(float v){
    float a = fabsf(v), e = __expf(-2.0f*a);
    float t = (1.0f - e)/(1.0f + e);
    return v < 0.0f ? -t : t;
}
// reduce over kh (lane bits 3,4): fixed order
__device__ __forceinline__ ull shred(ull v){
    v = add2(v, __shfl_xor_sync(0xffffffffu, v, 8));
    v = add2(v, __shfl_xor_sync(0xffffffffu, v, 16));
    return v;
}
// 2-level register tournament: pick a[kh] without dynamic indexing
__device__ __forceinline__ ull sel4(ull a0, ull a1, ull a2, ull a3, int kh){
    ull lo = (kh & 1) ? a1 : a0;
    ull hi = (kh & 1) ? a3 : a2;
    return (kh & 2) ? hi : lo;
}
__device__ __forceinline__ unsigned s2u(const void* p){
    unsigned a;
    asm("{ .reg .u64 t; cvta.to.shared.u64 t, %1; cvt.u32.u64 %0, t; }" : "=r"(a) : "l"(p));
    return a;
}
#define CP16(dst, src) asm volatile("cp.async.cg.shared.global [%0], [%1], 16;" :: "r"(dst), "l"(src) : "memory")
#define CPCOMMIT()     asm volatile("cp.async.commit_group;" ::: "memory")
#define CPWAIT(n)      asm volatile("cp.async.wait_group %0;" :: "n"(n) : "memory")

// publish: all CTA stores done (syncthreads) then leader release-store
__device__ __forceinline__ void postf(unsigned* f, int g, int p, unsigned val){
    __syncthreads();
    if (threadIdx.x == 0)
        asm volatile("st.release.gpu.global.u32 [%0], %1;" :: "l"(f + g*16 + p), "r"(val) : "memory");
}
// wait: 16 lanes poll 16 producer flags in parallel, then CTA-sync
__device__ __forceinline__ void waitf(unsigned* f, int g, unsigned target){
    if (threadIdx.x < 16) {
        const unsigned* a = f + g*16 + threadIdx.x;
        unsigned v;
        do {
            asm volatile("ld.acquire.gpu.global.u32 %0, [%1];" : "=r"(v) : "l"(a) : "memory");
        } while (v < target);
    }
    __syncthreads();
}

// ---------------- main persistent kernel ----------------
__global__ __launch_bounds__(NT, 1) void gru_main(
    const float* __restrict__ Wih0, const float* __restrict__ bih0, const float* __restrict__ bhh0,
    const float* __restrict__ bih1, const float* __restrict__ bhh1,
    const float* __restrict__ Wdih, const float* __restrict__ bdih, const float* __restrict__ bdhh,
    const float* __restrict__ Wo, const float* __restrict__ bo,
    float* __restrict__ out)
{
    extern __shared__ float sm[];
    float* sP1 = sm;               // [256][100] (8cp x 12 used)
    float* sP2 = sm + 25600;       // [256][50]  (8cp x 6 used)
    float* h0s = sP2 + 12800;      // [256 col][32 b]
    float* h1s = h0s + 8192;
    float* red2 = h1s + 8192;      // [32 b][8 cp]
    float* ybuf = red2 + 256;      // [32]

    const int p    = blockIdx.x & 15;
    const int g    = blockIdx.x >> 4;
    const int tid  = threadIdx.x;
    const int cp   = tid >> 5;
    const int lane = tid & 31;
    const int bq   = lane & 7;            // batch quad 0..7
    const int kh   = lane >> 3;           // k offset 0..3; also epilogue batch slot
    const int c0   = p*16 + cp*2;

    const unsigned h0u = s2u(h0s);
    const unsigned h1u = s2u(h1s);

    // stage weights + zero h tiles
    {
        const float4* a4 = (const float4*)(d_pP1 + p*25600);
        float4* da = (float4*)sP1;
        for (int i = tid; i < 6400; i += NT) da[i] = a4[i];
        const float4* b4 = (const float4*)(d_pP2 + p*12800);
        float4* db = (float4*)sP2;
        for (int i = tid; i < 3200; i += NT) db[i] = b4[i];
        float4 z = make_float4(0.f, 0.f, 0.f, 0.f);
        float4* zt = (float4*)h0s;
        for (int i = tid; i < 4096; i += NT) zt[i] = z;   // h0s + h1s contiguous
    }

    // per-thread gate constants; q = gate*2 + cl
    float wi0[6], bi0[6], bh0[6], bi1c[6], bh1c[6];
#pragma unroll
    for (int q = 0; q < 6; q++) {
        int j = (q >> 1)*256 + c0 + (q & 1);
        wi0[q] = Wih0[j]; bi0[q] = bih0[j]; bh0[q] = bhh0[j];
        bi1c[q] = bih1[j]; bh1c[q] = bhh1[j];
    }
    __syncthreads();

    // ============ encoder: 512 phases (layer0 t=u, layer1 t=u-1) ============
    for (int u = 0; u < 512; u++) {
        if (u > 0) {
            waitf(d_f0, g, (unsigned)u);            // h0(u) published by all
            const float4* s0 = (const float4*)(d_h0g + ((((u&1)^1)*NG + g) << 13));
#pragma unroll
            for (int i = 0; i < 8; i++) CP16(h0u + tid*16 + i*4096, s0 + tid + i*256);
            CPCOMMIT();
            CPWAIT(0);
            __syncthreads();
        }

        // ---- loop1: aA (Whh0 @ h0), aI (Wih1 @ h0) ----
        ull aA[12], aI[12];
#pragma unroll
        for (int i = 0; i < 12; i++) { aA[i] = 0ull; aI[i] = 0ull; }
        {
            const float4* h0p = (const float4*)(h0s + kh*32 + bq*4);
            const ulonglong2* w1p = (const ulonglong2*)(sP1 + kh*100 + cp*12);
            float4 hq = *h0p;
            ulonglong2 p0 = w1p[0], p1 = w1p[1], p2 = w1p[2];
#pragma unroll 4
            for (int kk = 0; kk < 64; kk++) {
                float4 hc = hq;
                ulonglong2 q0 = p0, q1 = p1, q2 = p2;
                if (kk != 63) {
                    h0p += 32; w1p += 100;
                    hq = *h0p; p0 = w1p[0]; p1 = w1p[1]; p2 = w1p[2];
                }
                const float* hf = (const float*)&hc;
#pragma unroll
                for (int bl = 0; bl < 4; bl++) {
                    ull hx = splat2(hf[bl]);
                    fma2(aA[0+bl], q0.x, hx);
                    fma2(aA[4+bl], q0.y, hx);
                    fma2(aA[8+bl], q1.x, hx);
                    fma2(aI[0+bl], q1.y, hx);
                    fma2(aI[4+bl], q2.x, hx);
                    fma2(aI[8+bl], q2.y, hx);
                }
            }
        }
#pragma unroll
        for (int i = 0; i < 12; i++) { aA[i] = shred(aA[i]); aI[i] = shred(aI[i]); }

        // ---- h1(u-1) arrival has ~loop1 of slack; fetch overlaps epilogue-0 ----
        if (u > 0) {
            waitf(d_f1, g, (unsigned)u);
            const float4* s1 = (const float4*)(d_h1g + ((((u&1)^1)*NG + g) << 13));
#pragma unroll
            for (int i = 0; i < 8; i++) CP16(h1u + tid*16 + i*4096, s1 + tid + i*256);
            CPCOMMIT();
        }

        // ---- epilogue-0 (ALL threads; bl = kh): h0(u+1) ----
        {
            float xv = d_xT[u*256 + g*32 + bq*4 + kh];
            float2 fr = unp(sel4(aA[0], aA[1], aA[2],  aA[3],  kh));
            float2 fz = unp(sel4(aA[4], aA[5], aA[6],  aA[7],  kh));
            float2 fn = unp(sel4(aA[8], aA[9], aA[10], aA[11], kh));
            float hold0 = h0s[c0*32 + bq*4 + kh];
            float hold1 = h0s[(c0+1)*32 + bq*4 + kh];
            float r0 = sigf(xv*wi0[0] + bi0[0] + fr.x + bh0[0]);
            float z0 = sigf(xv*wi0[2] + bi0[2] + fz.x + bh0[2]);
            float n0 = tanh_(xv*wi0[4] + bi0[4] + r0*(fn.x + bh0[4]));
            float r1 = sigf(xv*wi0[1] + bi0[1] + fr.y + bh0[1]);
            float z1 = sigf(xv*wi0[3] + bi0[3] + fz.y + bh0[3]);
            float n1 = tanh_(xv*wi0[5] + bi0[5] + r1*(fn.y + bh0[5]));
            float* dst = d_h0g + (((u&1)*NG + g) << 13) + c0*32 + bq*4 + kh;
            dst[0]  = (1.0f - z0)*n0 + z0*hold0;
            dst[32] = (1.0f - z1)*n1 + z1*hold1;
        }
        postf(d_f0, g, p, (unsigned)(u+1));

        if (u > 0) CPWAIT(0);
        __syncthreads();

        // ---- loop2: aH (Whh1 @ h1) ----
        ull aH[12];
#pragma unroll
        for (int i = 0; i < 12; i++) aH[i] = 0ull;
        {
            const float4* h1p = (const float4*)(h1s + kh*32 + bq*4);
            const ull* w2p = (const ull*)(sP2 + kh*50 + cp*6);
            float4 hq = *h1p;
            ull r0 = w2p[0], r1 = w2p[1], r2 = w2p[2];
#pragma unroll 4
            for (int kk = 0; kk < 64; kk++) {
                float4 hc = hq;
                ull q0 = r0, q1 = r1, q2 = r2;
                if (kk != 63) {
                    h1p += 32; w2p += 100;
                    hq = *h1p; r0 = w2p[0]; r1 = w2p[1]; r2 = w2p[2];
                }
                const float* hf = (const float*)&hc;
#pragma unroll
                for (int bl = 0; bl < 4; bl++) {
                    ull vx = splat2(hf[bl]);
                    fma2(aH[0+bl], q0, vx);
                    fma2(aH[4+bl], q1, vx);
                    fma2(aH[8+bl], q2, vx);
                }
            }
        }
#pragma unroll
        for (int i = 0; i < 12; i++) aH[i] = shred(aH[i]);

        // ---- epilogue-1 (ALL threads): h1(u), skip at u==0 ----
        if (u != 0) {
            float2 fir = unp(sel4(aI[0], aI[1], aI[2],  aI[3],  kh));
            float2 fiz = unp(sel4(aI[4], aI[5], aI[6],  aI[7],  kh));
            float2 fin = unp(sel4(aI[8], aI[9], aI[10], aI[11], kh));
            float2 fhr = unp(sel4(aH[0], aH[1], aH[2],  aH[3],  kh));
            float2 fhz = unp(sel4(aH[4], aH[5], aH[6],  aH[7],  kh));
            float2 fhn = unp(sel4(aH[8], aH[9], aH[10], aH[11], kh));
            float hold0 = h1s[c0*32 + bq*4 + kh];
            float hold1 = h1s[(c0+1)*32 + bq*4 + kh];
            float r0 = sigf(fir.x + bi1c[0] + fhr.x + bh1c[0]);
            float z0 = sigf(fiz.x + bi1c[2] + fhz.x + bh1c[2]);
            float n0 = tanh_(fin.x + bi1c[4] + r0*(fhn.x + bh1c[4]));
            float r1 = sigf(fir.y + bi1c[1] + fhr.y + bh1c[1]);
            float z1 = sigf(fiz.y + bi1c[3] + fhz.y + bh1c[3]);
            float n1 = tanh_(fin.y + bi1c[5] + r1*(fhn.y + bh1c[5]));
            float* dst = d_h1g + (((u&1)*NG + g) << 13) + c0*32 + bq*4 + kh;
            dst[0]  = (1.0f - z0)*n0 + z0*hold0;
            dst[32] = (1.0f - z1)*n1 + z1*hold1;
        }
        postf(d_f1, g, p, (unsigned)(u+1));
    }

    // ============ drain (phase 512): layer1 t=511 -> h1(512) ============
    {
        waitf(d_f0, g, 512u);
        waitf(d_f1, g, 512u);
        const float4* s0 = (const float4*)(d_h0g + ((1*NG + g) << 13));   // h0(512), parity 1
        const float4* s1 = (const float4*)(d_h1g + ((1*NG + g) << 13));   // h1(511), parity 1
#pragma unroll
        for (int i = 0; i < 8; i++) CP16(h0u + tid*16 + i*4096, s0 + tid + i*256);
#pragma unroll
        for (int i = 0; i < 8; i++) CP16(h1u + tid*16 + i*4096, s1 + tid + i*256);
        CPCOMMIT();
        CPWAIT(0);
        __syncthreads();

        ull aI[12], aH[12];
#pragma unroll
        for (int i = 0; i < 12; i++) { aI[i] = 0ull; aH[i] = 0ull; }
        {
            const float4* h0p = (const float4*)(h0s + kh*32 + bq*4);
            const float4* h1p = (const float4*)(h1s + kh*32 + bq*4);
            const ulonglong2* w1p = (const ulonglong2*)(sP1 + kh*100 + cp*12);
            const ull* w2p = (const ull*)(sP2 + kh*50 + cp*6);
#pragma unroll 4
            for (int kk = 0; kk < 64; kk++) {
                float4 u4 = *h0p; float4 v4 = *h1p;
                ulonglong2 p1 = w1p[1], p2 = w1p[2];
                ull r0 = w2p[0], r1 = w2p[1], r2 = w2p[2];
                const float* uf = (const float*)&u4;
                const float* vf = (const float*)&v4;
#pragma unroll
                for (int bl = 0; bl < 4; bl++) {
                    ull hx = splat2(uf[bl]);
                    fma2(aI[0+bl], p1.y, hx);
                    fma2(aI[4+bl], p2.x, hx);
                    fma2(aI[8+bl], p2.y, hx);
                    ull vx = splat2(vf[bl]);
                    fma2(aH[0+bl], r0, vx);
                    fma2(aH[4+bl], r1, vx);
                    fma2(aH[8+bl], r2, vx);
                }
                h0p += 32; h1p += 32; w1p += 100; w2p += 100;
            }
        }
#pragma unroll
        for (int i = 0; i < 12; i++) { aI[i] = shred(aI[i]); aH[i] = shred(aH[i]); }
        {
            float2 fir = unp(sel4(aI[0], aI[1], aI[2],  aI[3],  kh));
            float2 fiz = unp(sel4(aI[4], aI[5], aI[6],  aI[7],  kh));
            float2 fin = unp(sel4(aI[8], aI[9], aI[10], aI[11], kh));
            float2 fhr = unp(sel4(aH[0], aH[1], aH[2],  aH[3],  kh));
            float2 fhz = unp(sel4(aH[4], aH[5], aH[6],  aH[7],  kh));
            float2 fhn = unp(sel4(aH[8], aH[9], aH[10], aH[11], kh));
            float hold0 = h1s[c0*32 + bq*4 + kh];
            float hold1 = h1s[(c0+1)*32 + bq*4 + kh];
            float r0 = sigf(fir.x + bi1c[0] + fhr.x + bh1c[0]);
            float z0 = sigf(fiz.x + bi1c[2] + fhz.x + bh1c[2]);
            float n0 = tanh_(fin.x + bi1c[4] + r0*(fhn.x + bh1c[4]));
            float r1 = sigf(fir.y + bi1c[1] + fhr.y + bh1c[1]);
            float z1 = sigf(fiz.y + bi1c[3] + fhz.y + bh1c[3]);
            float n1 = tanh_(fin.y + bi1c[5] + r1*(fhn.y + bh1c[5]));
            float* dst = d_h1g + ((0*NG + g) << 13) + c0*32 + bq*4 + kh;   // h1(512), parity 0
            dst[0]  = (1.0f - z0)*n0 + z0*hold0;
            dst[32] = (1.0f - z1)*n1 + z1*hold1;
        }
        postf(d_f1, g, p, 513u);
    }

    // ============ decoder setup ============
    {
        const float4* a4 = (const float4*)(d_pD + p*12800);
        float4* da = (float4*)sP2;
        for (int i = tid; i < 3200; i += NT) da[i] = a4[i];
    }
    float wdi[6], bdi[6], bdh[6], wo0, wo1, bov;
#pragma unroll
    for (int q = 0; q < 6; q++) {
        int j = (q >> 1)*256 + c0 + (q & 1);
        wdi[q] = Wdih[j]; bdi[q] = bdih[j]; bdh[q] = bdhh[j];
    }
    wo0 = Wo[c0]; wo1 = Wo[c0 + 1]; bov = bo[0];

    // ============ decoder: 96 phases ============
    for (int t = 0; t < 96; t++) {
        waitf(d_f1, g, (unsigned)(513 + t));
        {   // async refresh h1 from parity t&1
            const float4* s1 = (const float4*)(d_h1g + (((t&1)*NG + g) << 13));
#pragma unroll
            for (int i = 0; i < 8; i++) CP16(h1u + tid*16 + i*4096, s1 + tid + i*256);
            CPCOMMIT();
        }
        if (t > 0 && tid < 32) {   // y(t-1) from party parity (t-1)&1; overlaps cp.async
            float s = bov;
#pragma unroll
            for (int q = 0; q < 16; q++)
                s += __ldcg(&d_party[((((t-1)&1)*NP + q)*NG + g)*32 + tid]);
            ybuf[tid] = s;
            if (p == 0) out[(g*32 + tid)*96 + (t-1)] = s;
        }
        CPWAIT(0);
        __syncthreads();

        float iv = (t > 0) ? ybuf[bq*4 + kh] : 0.0f;

        ull aD[12];
#pragma unroll
        for (int i = 0; i < 12; i++) aD[i] = 0ull;
        {
            const float4* h1p = (const float4*)(h1s + kh*32 + bq*4);
            const ull* w2p = (const ull*)(sP2 + kh*50 + cp*6);
            float4 hq = *h1p;
            ull r0 = w2p[0], r1 = w2p[1], r2 = w2p[2];
#pragma unroll 4
            for (int kk = 0; kk < 64; kk++) {
                float4 hc = hq;
                ull q0 = r0, q1 = r1, q2 = r2;
                if (kk != 63) {
                    h1p += 32; w2p += 100;
                    hq = *h1p; r0 = w2p[0]; r1 = w2p[1]; r2 = w2p[2];
                }
                const float* hf = (const float*)&hc;
#pragma unroll
                for (int bl = 0; bl < 4; bl++) {
                    ull vx = splat2(hf[bl]);
                    fma2(aD[0+bl], q0, vx);
                    fma2(aD[4+bl], q1, vx);
                    fma2(aD[8+bl], q2, vx);
                }
            }
        }
#pragma unroll
        for (int i = 0; i < 12; i++) aD[i] = shred(aD[i]);

        {   // epilogue (ALL threads; bl = kh)
            float2 fr = unp(sel4(aD[0], aD[1], aD[2],  aD[3],  kh));
            float2 fz = unp(sel4(aD[4], aD[5], aD[6],  aD[7],  kh));
            float2 fn = unp(sel4(aD[8], aD[9], aD[10], aD[11], kh));
            float hold0 = h1s[c0*32 + bq*4 + kh];
            float hold1 = h1s[(c0+1)*32 + bq*4 + kh];
            float r0 = sigf(iv*wdi[0] + bdi[0] + fr.x + bdh[0]);
            float z0 = sigf(iv*wdi[2] + bdi[2] + fz.x + bdh[2]);
            float n0 = tanh_(iv*wdi[4] + bdi[4] + r0*(fn.x + bdh[4]));
            float hv0 = (1.0f - z0)*n0 + z0*hold0;
            float r1 = sigf(iv*wdi[1] + bdi[1] + fr.y + bdh[1]);
            float z1 = sigf(iv*wdi[3] + bdi[3] + fz.y + bdh[3]);
            float n1 = tanh_(iv*wdi[5] + bdi[5] + r1*(fn.y + bdh[5]));
            float hv1 = (1.0f - z1)*n1 + z1*hold1;
            float* dst = d_h1g + ((((t+1)&1)*NG + g) << 13) + c0*32 + bq*4 + kh;
            dst[0]  = hv0;
            dst[32] = hv1;
            red2[(bq*4 + kh)*8 + cp] = hv0*wo0 + hv1*wo1;
        }
        __syncthreads();
        if (tid < 32) {   // partial over this CTA's 16 cols (fixed order), parity t&1
            float s = 0.f;
#pragma unroll
            for (int j = 0; j < 8; j++) s += red2[tid*8 + j];
            d_party[(((t&1)*NP + p)*NG + g)*32 + tid] = s;
        }
        postf(d_f1, g, p, (unsigned)(514 + t));
    }

    // final output (t = 95): party at parity 1
    if (p == 0) {
        waitf(d_f1, g, 609u);
        if (tid < 32) {
            float s = bov;
#pragma unroll
            for (int q = 0; q < 16; q++)
                s += __ldcg(&d_party[((1*NP + q)*NG + g)*32 + tid]);
            out[(g*32 + tid)*96 + 95] = s;
        }
    }
}

// ---------------- launch ----------------
extern "C" void kernel_launch(void* const* d_in, const int* in_sizes, int n_in,
                              void* d_out, int out_size)
{
    const float* x    = (const float*)d_in[0];
    const float* Wih0 = (const float*)d_in[1];
    const float* Whh0 = (const float*)d_in[2];
    const float* bih0 = (const float*)d_in[3];
    const float* bhh0 = (const float*)d_in[4];
    const float* Wih1 = (const float*)d_in[5];
    const float* Whh1 = (const float*)d_in[6];
    const float* bih1 = (const float*)d_in[7];
    const float* bhh1 = (const float*)d_in[8];
    const float* Wdih = (const float*)d_in[9];
    const float* Wdhh = (const float*)d_in[10];
    const float* bdih = (const float*)d_in[11];
    const float* bdhh = (const float*)d_in[12];
    const float* Wo   = (const float*)d_in[13];
    const float* bo   = (const float*)d_in[14];
    float* out = (float*)d_out;

    cudaFuncSetAttribute(gru_main, cudaFuncAttributeMaxDynamicSharedMemorySize, SMEM_BYTES);
    prep_kernel<<<384, 256>>>(Whh0, Wih1, Whh1, Wdhh, x);
    gru_main<<<NBLK, NT, SMEM_BYTES>>>(Wih0, bih0, bhh0, bih1, bhh1,
                                       Wdih, bdih, bdhh, Wo, bo, out);
}

// round 17
// speedup vs baseline: 1.6551x; 1.6551x over previous
#include <cuda_runtime.h>

typedef unsigned long long ull;

#define NG 8           // batch groups (32 batches each)
#define NP 16          // column partitions (16 hidden cols each)
#define NBLK (NG*NP)   // 128 CTAs
#define NT 256         // 8 warps
// smem floats: sP1 25600 + sP2 12800 + h0s 8192 + h1s 8192 + red2 256 + ybuf 32
#define SM_FLOATS (25600+12800+8192+8192+256+32)
#define SMEM_BYTES (SM_FLOATS*4)

// ---------------- static device scratch (no allocation) ----------------
__device__ float d_pP1[NP*256*100];   // [p][k(str100)][cp][ Whh0 r0 r1 z0 z1 n0 n1 | Wih1 ... ]
__device__ float d_pP2[NP*256*50];    // [p][k(str50)][cp][ Whh1 r0 r1 z0 z1 n0 n1 ]
__device__ float d_pD [NP*256*50];    // Wd_hh, same layout as P2
__device__ float d_xT[512*256];       // x transposed [t][b]
__device__ float d_h0g[2*NG*8192];    // [par][g][col256][b32]
__device__ float d_h1g[2*NG*8192];
__device__ float d_party[2*NP*NG*32]; // [par][p][g][b]
__device__ unsigned d_cnt[NG];        // aggregated counter: +16 per group at mid, +16 at end of each phase

// ---------------- prep ----------------
__global__ void prep_kernel(const float* __restrict__ Whh0, const float* __restrict__ Wih1,
                            const float* __restrict__ Whh1, const float* __restrict__ Wdhh,
                            const float* __restrict__ x)
{
    int idx = blockIdx.x*blockDim.x + threadIdx.x;
    int stride = gridDim.x*blockDim.x;
    if (idx < NG) d_cnt[idx] = 0u;
    for (int i = idx; i < NP*256*96; i += stride) {
        int q = i % 12, cp = (i/12) & 7, k = (i/96) & 255, p = i/24576;
        int qq = (q < 6) ? q : q - 6;
        int gate = qq >> 1, cl = qq & 1;
        int col = p*16 + cp*2 + cl;
        int src = (gate*256 + col)*256 + k;
        d_pP1[p*25600 + k*100 + cp*12 + q] = (q < 6) ? Whh0[src] : Wih1[src];
    }
    for (int i = idx; i < NP*256*48; i += stride) {
        int q = i % 6, cp = (i/6) & 7, k = (i/48) & 255, p = i/12288;
        int gate = q >> 1, cl = q & 1;
        int col = p*16 + cp*2 + cl;
        int src = (gate*256 + col)*256 + k;
        int dst = p*12800 + k*50 + cp*6 + q;
        d_pP2[dst] = Whh1[src];
        d_pD[dst]  = Wdhh[src];
    }
    for (int i = idx; i < 512*256; i += stride)
        d_xT[i] = x[(i & 255)*512 + (i >> 8)];
    for (int i = idx; i < 2*NG*8192; i += stride)
        d_h1g[i] = 0.0f;   // h1(0) reads must see zeros
}

// ---------------- helpers ----------------
__device__ __forceinline__ ull splat2(float v){ ull r; asm("mov.b64 %0, {%1,%1};" : "=l"(r) : "f"(v)); return r; }
__device__ __forceinline__ void fma2(ull &d, ull a, ull b){ asm("fma.rn.f32x2 %0, %1, %2, %0;" : "+l"(d) : "l"(a), "l"(b)); }
__device__ __forceinline__ ull add2(ull a, ull b){ ull r; asm("add.rn.f32x2 %0, %1, %2;" : "=l"(r) : "l"(a), "l"(b)); return r; }
__device__ __forceinline__ float2 unp(ull v){ float2 f; asm("mov.b64 {%0,%1}, %2;" : "=f"(f.x), "=f"(f.y) : "l"(v)); return f; }
__device__ __forceinline__ float sigf(float v){ return 1.0f/(1.0f + __expf(-v)); }
__device__ __forceinline__ float tanh_(float v){
    float a = fabsf(v), e = __expf(-2.0f*a);
    float t = (1.0f - e)/(1.0f + e);
    return v < 0.0f ? -t : t;
}
// reduce over kh (lane bits 3,4): fixed order
__device__ __forceinline__ ull shred(ull v){
    v = add2(v, __shfl_xor_sync(0xffffffffu, v, 8));
    v = add2(v, __shfl_xor_sync(0xffffffffu, v, 16));
    return v;
}
// register tournament: pick a[kh] without dynamic indexing
__device__ __forceinline__ ull sel4(ull a0, ull a1, ull a2, ull a3, int kh){
    ull lo = (kh & 1) ? a1 : a0;
    ull hi = (kh & 1) ? a3 : a2;
    return (kh & 2) ? hi : lo;
}
__device__ __forceinline__ unsigned s2u(const void* p){
    unsigned a;
    asm("{ .reg .u64 t; cvta.to.shared.u64 t, %1; cvt.u32.u64 %0, t; }" : "=r"(a) : "l"(p));
    return a;
}
#define CP16(dst, src) asm volatile("cp.async.cg.shared.global [%0], [%1], 16;" :: "r"(dst), "l"(src) : "memory")
#define CPCOMMIT()     asm volatile("cp.async.commit_group;" ::: "memory")
#define CPWAIT(n)      asm volatile("cp.async.wait_group %0;" :: "n"(n) : "memory")

// leader release-add WITHOUT its own syncthreads (caller provides the ordering sync)
__device__ __forceinline__ void post_leader(int g){
    if (threadIdx.x == 0)
        asm volatile("red.release.gpu.global.add.u32 [%0], %1;" :: "l"(d_cnt + g), "r"(1u) : "memory");
}
// leader poll + CTA sync (R14-proven)
__device__ __forceinline__ void gwait(int g, unsigned target){
    if (threadIdx.x == 0) {
        unsigned v;
        do {
            asm volatile("ld.acquire.gpu.global.u32 %0, [%1];" : "=r"(v) : "l"(d_cnt + g) : "memory");
        } while (v < target);
    }
    __syncthreads();
}

// ---------------- main persistent kernel ----------------
__global__ __launch_bounds__(NT, 1) void gru_main(
    const float* __restrict__ Wih0, const float* __restrict__ bih0, const float* __restrict__ bhh0,
    const float* __restrict__ bih1, const float* __restrict__ bhh1,
    const float* __restrict__ Wdih, const float* __restrict__ bdih, const float* __restrict__ bdhh,
    const float* __restrict__ Wo, const float* __restrict__ bo,
    float* __restrict__ out)
{
    extern __shared__ float sm[];
    float* sP1 = sm;               // [256][100] (8cp x 12 used)
    float* sP2 = sm + 25600;       // [256][50]  (8cp x 6 used)
    float* h0s = sP2 + 12800;      // [256 col][32 b]
    float* h1s = h0s + 8192;
    float* red2 = h1s + 8192;      // [32 b][8 cp]
    float* ybuf = red2 + 256;      // [32]

    const int p    = blockIdx.x & 15;
    const int g    = blockIdx.x >> 4;
    const int tid  = threadIdx.x;
    const int cp   = tid >> 5;
    const int lane = tid & 31;
    const int bq   = lane & 7;            // batch quad 0..7
    const int kh   = lane >> 3;           // k offset 0..3; also epilogue batch slot (bl = kh)
    const int c0   = p*16 + cp*2;

    const unsigned h0u = s2u(h0s);
    const unsigned h1u = s2u(h1s);

    // stage weights + zero h tiles
    {
        const float4* a4 = (const float4*)(d_pP1 + p*25600);
        float4* da = (float4*)sP1;
        for (int i = tid; i < 6400; i += NT) da[i] = a4[i];
        const float4* b4 = (const float4*)(d_pP2 + p*12800);
        float4* db = (float4*)sP2;
        for (int i = tid; i < 3200; i += NT) db[i] = b4[i];
        float4 z = make_float4(0.f, 0.f, 0.f, 0.f);
        float4* zt = (float4*)h0s;
        for (int i = tid; i < 4096; i += NT) zt[i] = z;   // h0s + h1s contiguous
    }

    // per-thread gate constants; q = gate*2 + cl
    float wi0[6], bi0[6], bh0[6], bi1c[6], bh1c[6];
#pragma unroll
    for (int q = 0; q < 6; q++) {
        int j = (q >> 1)*256 + c0 + (q & 1);
        wi0[q] = Wih0[j]; bi0[q] = bih0[j]; bh0[q] = bhh0[j];
        bi1c[q] = bih1[j]; bh1c[q] = bhh1[j];
    }
    __syncthreads();

    // counter protocol: phase u adds 16 at mid (h0(u+1) published) and 16 at end
    // (h1(u) published). After phase u fully done: count = 32(u+1).

    // ============ encoder: 512 phases (layer0 t=u, layer1 t=u-1) ============
    for (int u = 0; u < 512; u++) {
        if (u > 0) {
            gwait(g, 32u*(unsigned)u - 16u);        // h0(u) published (mid of phase u-1)
            const float4* s0 = (const float4*)(d_h0g + ((((u&1)^1)*NG + g) << 13));
#pragma unroll
            for (int i = 0; i < 8; i++) CP16(h0u + tid*16 + i*4096, s0 + tid + i*256);
            CPCOMMIT();
            CPWAIT(0);
            __syncthreads();
        }

        // ---- loop1: aA (Whh0 @ h0), aI (Wih1 @ h0) ----
        ull aA[12], aI[12];
#pragma unroll
        for (int i = 0; i < 12; i++) { aA[i] = 0ull; aI[i] = 0ull; }
        {
            const float4* h0p = (const float4*)(h0s + kh*32 + bq*4);
            const ulonglong2* w1p = (const ulonglong2*)(sP1 + kh*100 + cp*12);
            float4 hq = *h0p;
            ulonglong2 p0 = w1p[0], p1 = w1p[1], p2 = w1p[2];
#pragma unroll 4
            for (int kk = 0; kk < 64; kk++) {
                float4 hc = hq;
                ulonglong2 q0 = p0, q1 = p1, q2 = p2;
                if (kk != 63) {
                    h0p += 32; w1p += 100;
                    hq = *h0p; p0 = w1p[0]; p1 = w1p[1]; p2 = w1p[2];
                }
                const float* hf = (const float*)&hc;
#pragma unroll
                for (int bl = 0; bl < 4; bl++) {
                    ull hx = splat2(hf[bl]);
                    fma2(aA[0+bl], q0.x, hx);
                    fma2(aA[4+bl], q0.y, hx);
                    fma2(aA[8+bl], q1.x, hx);
                    fma2(aI[0+bl], q1.y, hx);
                    fma2(aI[4+bl], q2.x, hx);
                    fma2(aI[8+bl], q2.y, hx);
                }
            }
        }
#pragma unroll
        for (int i = 0; i < 12; i++) { aA[i] = shred(aA[i]); aI[i] = shred(aI[i]); }

        // ---- wait h1(u-1) (end posts of phase u-1; ~loop1 stale by now) + fetch ----
        if (u > 0) {
            gwait(g, 32u*(unsigned)u);
            const float4* s1 = (const float4*)(d_h1g + ((((u&1)^1)*NG + g) << 13));
#pragma unroll
            for (int i = 0; i < 8; i++) CP16(h1u + tid*16 + i*4096, s1 + tid + i*256);
            CPCOMMIT();
        }

        // ---- epilogue-0 (ALL threads; bl = kh): h0(u+1) ----
        {
            float xv = d_xT[u*256 + g*32 + bq*4 + kh];
            float2 fr = unp(sel4(aA[0], aA[1], aA[2],  aA[3],  kh));
            float2 fz = unp(sel4(aA[4], aA[5], aA[6],  aA[7],  kh));
            float2 fn = unp(sel4(aA[8], aA[9], aA[10], aA[11], kh));
            float hold0 = h0s[c0*32 + bq*4 + kh];
            float hold1 = h0s[(c0+1)*32 + bq*4 + kh];
            float r0 = sigf(xv*wi0[0] + bi0[0] + fr.x + bh0[0]);
            float z0 = sigf(xv*wi0[2] + bi0[2] + fz.x + bh0[2]);
            float n0 = tanh_(xv*wi0[4] + bi0[4] + r0*(fn.x + bh0[4]));
            float r1 = sigf(xv*wi0[1] + bi0[1] + fr.y + bh0[1]);
            float z1 = sigf(xv*wi0[3] + bi0[3] + fz.y + bh0[3]);
            float n1 = tanh_(xv*wi0[5] + bi0[5] + r1*(fn.y + bh0[5]));
            float* dst = d_h0g + (((u&1)*NG + g) << 13) + c0*32 + bq*4 + kh;
            dst[0]  = (1.0f - z0)*n0 + z0*hold0;
            dst[32] = (1.0f - z1)*n1 + z1*hold1;
        }

        CPWAIT(0);              // h1 tile landed
        __syncthreads();        // orders epilogue-0 stores for the mid post AND h1 smem visibility
        post_leader(g);         // mid post: h0(u+1) published -> count 32u+16 once all 16 posted

        // ---- loop2: aH (Whh1 @ h1) ----
        ull aH[12];
#pragma unroll
        for (int i = 0; i < 12; i++) aH[i] = 0ull;
        {
            const float4* h1p = (const float4*)(h1s + kh*32 + bq*4);
            const ull* w2p = (const ull*)(sP2 + kh*50 + cp*6);
            float4 hq = *h1p;
            ull r0 = w2p[0], r1 = w2p[1], r2 = w2p[2];
#pragma unroll 4
            for (int kk = 0; kk < 64; kk++) {
                float4 hc = hq;
                ull q0 = r0, q1 = r1, q2 = r2;
                if (kk != 63) {
                    h1p += 32; w2p += 100;
                    hq = *h1p; r0 = w2p[0]; r1 = w2p[1]; r2 = w2p[2];
                }
                const float* hf = (const float*)&hc;
#pragma unroll
                for (int bl = 0; bl < 4; bl++) {
                    ull vx = splat2(hf[bl]);
                    fma2(aH[0+bl], q0, vx);
                    fma2(aH[4+bl], q1, vx);
                    fma2(aH[8+bl], q2, vx);
                }
            }
        }
#pragma unroll
        for (int i = 0; i < 12; i++) aH[i] = shred(aH[i]);

        // ---- epilogue-1 (ALL threads): h1(u), skip at u==0 ----
        if (u != 0) {
            float2 fir = unp(sel4(aI[0], aI[1], aI[2],  aI[3],  kh));
            float2 fiz = unp(sel4(aI[4], aI[5], aI[6],  aI[7],  kh));
            float2 fin = unp(sel4(aI[8], aI[9], aI[10], aI[11], kh));
            float2 fhr = unp(sel4(aH[0], aH[1], aH[2],  aH[3],  kh));
            float2 fhz = unp(sel4(aH[4], aH[5], aH[6],  aH[7],  kh));
            float2 fhn = unp(sel4(aH[8], aH[9], aH[10], aH[11], kh));
            float hold0 = h1s[c0*32 + bq*4 + kh];
            float hold1 = h1s[(c0+1)*32 + bq*4 + kh];
            float r0 = sigf(fir.x + bi1c[0] + fhr.x + bh1c[0]);
            float z0 = sigf(fiz.x + bi1c[2] + fhz.x + bh1c[2]);
            float n0 = tanh_(fin.x + bi1c[4] + r0*(fhn.x + bh1c[4]));
            float r1 = sigf(fir.y + bi1c[1] + fhr.y + bh1c[1]);
            float z1 = sigf(fiz.y + bi1c[3] + fhz.y + bh1c[3]);
            float n1 = tanh_(fin.y + bi1c[5] + r1*(fhn.y + bh1c[5]));
            float* dst = d_h1g + (((u&1)*NG + g) << 13) + c0*32 + bq*4 + kh;
            dst[0]  = (1.0f - z0)*n0 + z0*hold0;
            dst[32] = (1.0f - z1)*n1 + z1*hold1;
        }
        __syncthreads();        // orders epilogue-1 stores for the end post
        post_leader(g);         // end post: h1(u) published -> count 32(u+1)
    }

    // ============ drain (phase 512): layer1 t=511 -> h1(512) ============
    {
        gwait(g, 32u*512u);     // = 16384: h0(512) and h1(511) both published
        const float4* s0 = (const float4*)(d_h0g + ((1*NG + g) << 13));   // h0(512), parity 1
        const float4* s1 = (const float4*)(d_h1g + ((1*NG + g) << 13));   // h1(511), parity 1
#pragma unroll
        for (int i = 0; i < 8; i++) CP16(h0u + tid*16 + i*4096, s0 + tid + i*256);
#pragma unroll
        for (int i = 0; i < 8; i++) CP16(h1u + tid*16 + i*4096, s1 + tid + i*256);
        CPCOMMIT();
        CPWAIT(0);
        __syncthreads();

        ull aI[12], aH[12];
#pragma unroll
        for (int i = 0; i < 12; i++) { aI[i] = 0ull; aH[i] = 0ull; }
        {
            const float4* h0p = (const float4*)(h0s + kh*32 + bq*4);
            const float4* h1p = (const float4*)(h1s + kh*32 + bq*4);
            const ulonglong2* w1p = (const ulonglong2*)(sP1 + kh*100 + cp*12);
            const ull* w2p = (const ull*)(sP2 + kh*50 + cp*6);
#pragma unroll 4
            for (int kk = 0; kk < 64; kk++) {
                float4 u4 = *h0p; float4 v4 = *h1p;
                ulonglong2 p1 = w1p[1], p2 = w1p[2];
                ull r0 = w2p[0], r1 = w2p[1], r2 = w2p[2];
                const float* uf = (const float*)&u4;
                const float* vf = (const float*)&v4;
#pragma unroll
                for (int bl = 0; bl < 4; bl++) {
                    ull hx = splat2(uf[bl]);
                    fma2(aI[0+bl], p1.y, hx);
                    fma2(aI[4+bl], p2.x, hx);
                    fma2(aI[8+bl], p2.y, hx);
                    ull vx = splat2(vf[bl]);
                    fma2(aH[0+bl], r0, vx);
                    fma2(aH[4+bl], r1, vx);
                    fma2(aH[8+bl], r2, vx);
                }
                h0p += 32; h1p += 32; w1p += 100; w2p += 100;
            }
        }
#pragma unroll
        for (int i = 0; i < 12; i++) { aI[i] = shred(aI[i]); aH[i] = shred(aH[i]); }
        {
            float2 fir = unp(sel4(aI[0], aI[1], aI[2],  aI[3],  kh));
            float2 fiz = unp(sel4(aI[4], aI[5], aI[6],  aI[7],  kh));
            float2 fin = unp(sel4(aI[8], aI[9], aI[10], aI[11], kh));
            float2 fhr = unp(sel4(aH[0], aH[1], aH[2],  aH[3],  kh));
            float2 fhz = unp(sel4(aH[4], aH[5], aH[6],  aH[7],  kh));
            float2 fhn = unp(sel4(aH[8], aH[9], aH[10], aH[11], kh));
            float hold0 = h1s[c0*32 + bq*4 + kh];
            float hold1 = h1s[(c0+1)*32 + bq*4 + kh];
            float r0 = sigf(fir.x + bi1c[0] + fhr.x + bh1c[0]);
            float z0 = sigf(fiz.x + bi1c[2] + fhz.x + bh1c[2]);
            float n0 = tanh_(fin.x + bi1c[4] + r0*(fhn.x + bh1c[4]));
            float r1 = sigf(fir.y + bi1c[1] + fhr.y + bh1c[1]);
            float z1 = sigf(fiz.y + bi1c[3] + fhz.y + bh1c[3]);
            float n1 = tanh_(fin.y + bi1c[5] + r1*(fhn.y + bh1c[5]));
            float* dst = d_h1g + ((0*NG + g) << 13) + c0*32 + bq*4 + kh;   // h1(512), parity 0
            dst[0]  = (1.0f - z0)*n0 + z0*hold0;
            dst[32] = (1.0f - z1)*n1 + z1*hold1;
        }
        __syncthreads();
        post_leader(g);          // -> 16400
    }

    // ============ decoder setup ============
    {
        const float4* a4 = (const float4*)(d_pD + p*12800);
        float4* da = (float4*)sP2;
        for (int i = tid; i < 3200; i += NT) da[i] = a4[i];
    }
    float wdi[6], bdi[6], bdh[6], wo0, wo1, bov;
#pragma unroll
    for (int q = 0; q < 6; q++) {
        int j = (q >> 1)*256 + c0 + (q & 1);
        wdi[q] = Wdih[j]; bdi[q] = bdih[j]; bdh[q] = bdhh[j];
    }
    wo0 = Wo[c0]; wo1 = Wo[c0 + 1]; bov = bo[0];

    // ============ decoder: 96 phases (one post each) ============
    for (int t = 0; t < 96; t++) {
        gwait(g, 16400u + 16u*(unsigned)t);   // h1(512+t) published
        {   // async refresh h1 from parity t&1
            const float4* s1 = (const float4*)(d_h1g + (((t&1)*NG + g) << 13));
#pragma unroll
            for (int i = 0; i < 8; i++) CP16(h1u + tid*16 + i*4096, s1 + tid + i*256);
            CPCOMMIT();
        }
        if (t > 0 && tid < 32) {   // y(t-1) from party parity (t-1)&1; overlaps cp.async
            float s = bov;
#pragma unroll
            for (int q = 0; q < 16; q++)
                s += __ldcg(&d_party[((((t-1)&1)*NP + q)*NG + g)*32 + tid]);
            ybuf[tid] = s;
            if (p == 0) out[(g*32 + tid)*96 + (t-1)] = s;
        }
        CPWAIT(0);
        __syncthreads();

        float iv = (t > 0) ? ybuf[bq*4 + kh] : 0.0f;

        ull aD[12];
#pragma unroll
        for (int i = 0; i < 12; i++) aD[i] = 0ull;
        {
            const float4* h1p = (const float4*)(h1s + kh*32 + bq*4);
            const ull* w2p = (const ull*)(sP2 + kh*50 + cp*6);
            float4 hq = *h1p;
            ull r0 = w2p[0], r1 = w2p[1], r2 = w2p[2];
#pragma unroll 4
            for (int kk = 0; kk < 64; kk++) {
                float4 hc = hq;
                ull q0 = r0, q1 = r1, q2 = r2;
                if (kk != 63) {
                    h1p += 32; w2p += 100;
                    hq = *h1p; r0 = w2p[0]; r1 = w2p[1]; r2 = w2p[2];
                }
                const float* hf = (const float*)&hc;
#pragma unroll
                for (int bl = 0; bl < 4; bl++) {
                    ull vx = splat2(hf[bl]);
                    fma2(aD[0+bl], q0, vx);
                    fma2(aD[4+bl], q1, vx);
                    fma2(aD[8+bl], q2, vx);
                }
            }
        }
#pragma unroll
        for (int i = 0; i < 12; i++) aD[i] = shred(aD[i]);

        {   // epilogue (ALL threads; bl = kh)
            float2 fr = unp(sel4(aD[0], aD[1], aD[2],  aD[3],  kh));
            float2 fz = unp(sel4(aD[4], aD[5], aD[6],  aD[7],  kh));
            float2 fn = unp(sel4(aD[8], aD[9], aD[10], aD[11], kh));
            float hold0 = h1s[c0*32 + bq*4 + kh];
            float hold1 = h1s[(c0+1)*32 + bq*4 + kh];
            float r0 = sigf(iv*wdi[0] + bdi[0] + fr.x + bdh[0]);
            float z0 = sigf(iv*wdi[2] + bdi[2] + fz.x + bdh[2]);
            float n0 = tanh_(iv*wdi[4] + bdi[4] + r0*(fn.x + bdh[4]));
            float hv0 = (1.0f - z0)*n0 + z0*hold0;
            float r1 = sigf(iv*wdi[1] + bdi[1] + fr.y + bdh[1]);
            float z1 = sigf(iv*wdi[3] + bdi[3] + fz.y + bdh[3]);
            float n1 = tanh_(iv*wdi[5] + bdi[5] + r1*(fn.y + bdh[5]));
            float hv1 = (1.0f - z1)*n1 + z1*hold1;
            float* dst = d_h1g + ((((t+1)&1)*NG + g) << 13) + c0*32 + bq*4 + kh;
            dst[0]  = hv0;
            dst[32] = hv1;
            red2[(bq*4 + kh)*8 + cp] = hv0*wo0 + hv1*wo1;
        }
        __syncthreads();
        if (tid < 32) {   // partial over this CTA's 16 cols (fixed order), parity t&1
            float s = 0.f;
#pragma unroll
            for (int j = 0; j < 8; j++) s += red2[tid*8 + j];
            d_party[(((t&1)*NP + p)*NG + g)*32 + tid] = s;
        }
        __syncthreads();
        post_leader(g);    // -> 16400 + 16(t+1)
    }

    // final output (t = 95): party at parity 1
    if (p == 0) {
        gwait(g, 16400u + 16u*96u);
        if (tid < 32) {
            float s = bov;
#pragma unroll
            for (int q = 0; q < 16; q++)
                s += __ldcg(&d_party[((1*NP + q)*NG + g)*32 + tid]);
            out[(g*32 + tid)*96 + 95] = s;
        }
    }
}

// ---------------- launch ----------------
extern "C" void kernel_launch(void* const* d_in, const int* in_sizes, int n_in,
                              void* d_out, int out_size)
{
    const float* x    = (const float*)d_in[0];
    const float* Wih0 = (const float*)d_in[1];
    const float* Whh0 = (const float*)d_in[2];
    const float* bih0 = (const float*)d_in[3];
    const float* bhh0 = (const float*)d_in[4];
    const float* Wih1 = (const float*)d_in[5];
    const float* Whh1 = (const float*)d_in[6];
    const float* bih1 = (const float*)d_in[7];
    const float* bhh1 = (const float*)d_in[8];
    const float* Wdih = (const float*)d_in[9];
    const float* Wdhh = (const float*)d_in[10];
    const float* bdih = (const float*)d_in[11];
    const float* bdhh = (const float*)d_in[12];
    const float* Wo   = (const float*)d_in[13];
    const float* bo   = (const float*)d_in[14];
    float* out = (float*)d_out;

    cudaFuncSetAttribute(gru_main, cudaFuncAttributeMaxDynamicSharedMemorySize, SMEM_BYTES);
    prep_kernel<<<384, 256>>>(Whh0, Wih1, Whh1, Wdhh, x);
    gru_main<<<NBLK, NT, SMEM_BYTES>>>(Wih0, bih0, bhh0, bih1, bhh1,
                                       Wdih, bdih, bdhh, Wo, bo, out);
}